// round 1
// baseline (speedup 1.0000x reference)
#include <cuda_runtime.h>

// Problem constants
#define B_    16384
#define S_    200
#define N_    6
#define H_    50
#define T_    5
#define KH    25          // hidden slice per role (2 roles per batch)
#define NB    128         // batches per CTA
#define THREADS 256       // 2 threads per batch

// SMEM layout (in floats).
// Transposed weights: for each n in [0,56): 4 gates x 2 roles x 32 (25 used, padded)
#define WT_SIZE (56 * 256)
#define OFF_WTE 0
#define OFF_WTD (OFF_WTE + WT_SIZE)
#define OFF_BE  (OFF_WTD + WT_SIZE)          // 200
#define OFF_BD  (OFF_BE + 200)               // 200
#define OFF_WL  (OFF_BD + 200)               // 6*50 = 300
#define OFF_BL  (OFF_WL + 300)               // 8 (6 used)
#define OFF_HS  (OFF_BL + 8)                 // double buffer: 2 * NB * H_
#define HS_SIZE (NB * H_)
#define OFF_PP  (OFF_HS + 2 * HS_SIZE)       // NB * 12 partial preds
#define SMEM_FLOATS (OFF_PP + NB * 12)

__device__ __forceinline__ float sigm(float x) {
    // 1/(1+exp(-x)) via MUFU.EX2 + MUFU.RCP (high accuracy, cheap)
    return __fdividef(1.0f, 1.0f + __expf(-x));
}
__device__ __forceinline__ float tanha(float x) {
    // tanh(x) = 2*sigmoid(2x) - 1
    return __fdividef(2.0f, 1.0f + __expf(-2.0f * x)) - 1.0f;
}

// One "row" of the MAC: acc[g][k] += v * W[g*50 + kb + k][n] for this thread's 25 k's, 4 gates.
// w points at Wt[n] segment for this thread's role; gate segments are 64 floats apart, 128B aligned.
__device__ __forceinline__ void mac_row(float (*acc)[KH], const float* __restrict__ w, float v) {
    #pragma unroll
    for (int g = 0; g < 4; ++g) {
        const float* wg = w + g * 64;
        #pragma unroll
        for (int q = 0; q < 6; ++q) {
            float4 w4 = *reinterpret_cast<const float4*>(wg + 4 * q);
            acc[g][4 * q + 0] = fmaf(v, w4.x, acc[g][4 * q + 0]);
            acc[g][4 * q + 1] = fmaf(v, w4.y, acc[g][4 * q + 1]);
            acc[g][4 * q + 2] = fmaf(v, w4.z, acc[g][4 * q + 2]);
            acc[g][4 * q + 3] = fmaf(v, w4.w, acc[g][4 * q + 3]);
        }
        acc[g][24] = fmaf(v, wg[24], acc[g][24]);
    }
}

// One LSTM cell step for this thread's slice.
// wt:   transposed weight base (already offset by role: +r*32)
// bias: combined bias (bih+bhh), 200 floats
// xc:   current input x[6] in registers
// hcur: SMEM base of current-h for this batch (50 floats)
// hnxt: SMEM dest for this thread's 25 new h values
// c:    register cell state (25)
// hreg: out: the 25 new h values (registers)
__device__ __forceinline__ void cell_step(
    const float* __restrict__ wt, const float* __restrict__ bias, int kb,
    const float xc[6], const float* __restrict__ hcur, float* __restrict__ hnxt,
    float* __restrict__ c, float* __restrict__ hreg)
{
    float acc[4][KH];
    #pragma unroll
    for (int g = 0; g < 4; ++g)
        #pragma unroll
        for (int k = 0; k < KH; ++k)
            acc[g][k] = bias[g * H_ + kb + k];

    // x contribution (n = 0..5)
    #pragma unroll
    for (int n = 0; n < N_; ++n)
        mac_row(acc, wt + n * 256, xc[n]);

    // h contribution (n = 6..55)
    #pragma unroll 2
    for (int n = 0; n < H_; ++n) {
        float hv = hcur[n];
        mac_row(acc, wt + (N_ + n) * 256, hv);
    }

    // gates + state update
    #pragma unroll
    for (int k = 0; k < KH; ++k) {
        float ig = sigm(acc[0][k]);
        float fg = sigm(acc[1][k]);
        float gg = tanha(acc[2][k]);
        float og = sigm(acc[3][k]);
        float cn = fmaf(fg, c[k], ig * gg);
        c[k] = cn;
        float hn = og * tanha(cn);
        hreg[k] = hn;
        hnxt[k] = hn;
    }
}

__global__ void __launch_bounds__(THREADS, 1)
TemPred_kernel(const float* __restrict__ x_seq,
               const float* __restrict__ Wih_e, const float* __restrict__ Whh_e,
               const float* __restrict__ bih_e, const float* __restrict__ bhh_e,
               const float* __restrict__ Wih_d, const float* __restrict__ Whh_d,
               const float* __restrict__ bih_d, const float* __restrict__ bhh_d,
               const float* __restrict__ Wl, const float* __restrict__ bl,
               float* __restrict__ out)
{
    extern __shared__ float sm[];
    const int tid = threadIdx.x;

    // ---- stage weights into SMEM (transposed + padded layout) ----
    for (int idx = tid; idx < WT_SIZE; idx += THREADS) {
        int n   = idx >> 8;          // 0..55
        int rem = idx & 255;
        int g   = rem >> 6;          // 0..3
        int rr  = (rem >> 5) & 1;    // role
        int k   = rem & 31;          // 0..31 (25 used)
        float ve = 0.f, vd = 0.f;
        if (k < KH) {
            int j = g * H_ + rr * KH + k;      // gate row index
            if (n < N_) {
                ve = Wih_e[j * N_ + n];
                vd = Wih_d[j * N_ + n];
            } else {
                ve = Whh_e[j * H_ + (n - N_)];
                vd = Whh_d[j * H_ + (n - N_)];
            }
        }
        sm[OFF_WTE + idx] = ve;
        sm[OFF_WTD + idx] = vd;
    }
    for (int j = tid; j < 200; j += THREADS) {
        sm[OFF_BE + j] = bih_e[j] + bhh_e[j];
        sm[OFF_BD + j] = bih_d[j] + bhh_d[j];
    }
    for (int i = tid; i < 300; i += THREADS) sm[OFF_WL + i] = Wl[i];
    if (tid < N_) sm[OFF_BL + tid] = bl[tid];
    // zero h buffer 0
    for (int i = tid; i < HS_SIZE; i += THREADS) sm[OFF_HS + i] = 0.f;
    __syncthreads();

    const int bloc = tid >> 1;                 // local batch index
    const int r    = tid & 1;                  // role (which 25 of H)
    const int b    = blockIdx.x * NB + bloc;   // global batch (exact: 128*128=16384)
    const int kb   = r * KH;

    float c[KH];
    #pragma unroll
    for (int k = 0; k < KH; ++k) c[k] = 0.f;

    float xc[N_], xn[N_], hreg[KH];
    const float* xb = x_seq + (long)b * (S_ * N_);
    #pragma unroll
    for (int m = 0; m < N_; ++m) xc[m] = __ldg(xb + m);

    int cur = 0;
    const float* wte = sm + OFF_WTE + r * 32;
    const float* wtd = sm + OFF_WTD + r * 32;

    // ================= encoder =================
    for (int t = 0; t < S_; ++t) {
        if (t + 1 < S_) {
            #pragma unroll
            for (int m = 0; m < N_; ++m) xn[m] = __ldg(xb + (t + 1) * N_ + m);
        }
        const float* hcur = sm + OFF_HS + cur * HS_SIZE + bloc * H_;
        float* hnxt = sm + OFF_HS + (cur ^ 1) * HS_SIZE + bloc * H_ + kb;
        cell_step(wte, sm + OFF_BE, kb, xc, hcur, hnxt, c, hreg);
        cur ^= 1;
        __syncthreads();
        if (t + 1 < S_) {
            #pragma unroll
            for (int m = 0; m < N_; ++m) xc[m] = xn[m];
        }
    }
    // xc now holds x at t = S-1, which is the first decoder input.

    // ================= decoder =================
    for (int t = 0; t < T_; ++t) {
        const float* hcur = sm + OFF_HS + cur * HS_SIZE + bloc * H_;
        float* hnxt = sm + OFF_HS + (cur ^ 1) * HS_SIZE + bloc * H_ + kb;
        cell_step(wtd, sm + OFF_BD, kb, xc, hcur, hnxt, c, hreg);
        cur ^= 1;
        __syncthreads();

        // linear head: partial over this thread's 25 h values
        float* pp = sm + OFF_PP + bloc * 12 + r * 6;
        #pragma unroll
        for (int m = 0; m < N_; ++m) {
            float s = 0.f;
            const float* wl = sm + OFF_WL + m * H_ + kb;
            #pragma unroll
            for (int k = 0; k < KH; ++k) s = fmaf(wl[k], hreg[k], s);
            pp[m] = s;
        }
        __syncthreads();

        const float* pp0 = sm + OFF_PP + bloc * 12;
        #pragma unroll
        for (int m = 0; m < N_; ++m)
            xc[m] = pp0[m] + pp0[6 + m] + sm[OFF_BL + m];

        if (r == 0) {
            float* o = out + (long)b * (T_ * N_) + t * N_;
            #pragma unroll
            for (int m = 0; m < N_; ++m) o[m] = xc[m];
        }
        // No extra barrier needed: next write to pp happens only after the next
        // cell_step's __syncthreads, which orders these reads before it.
    }
}

extern "C" void kernel_launch(void* const* d_in, const int* in_sizes, int n_in,
                              void* d_out, int out_size)
{
    (void)in_sizes; (void)n_in; (void)out_size;
    const float* x_seq = (const float*)d_in[0];
    const float* Wih_e = (const float*)d_in[1];
    const float* Whh_e = (const float*)d_in[2];
    const float* bih_e = (const float*)d_in[3];
    const float* bhh_e = (const float*)d_in[4];
    const float* Wih_d = (const float*)d_in[5];
    const float* Whh_d = (const float*)d_in[6];
    const float* bih_d = (const float*)d_in[7];
    const float* bhh_d = (const float*)d_in[8];
    const float* Wl    = (const float*)d_in[9];
    const float* bl    = (const float*)d_in[10];
    float* out = (float*)d_out;

    size_t smem_bytes = SMEM_FLOATS * sizeof(float);   // ~175 KB
    cudaFuncSetAttribute(TemPred_kernel,
                         cudaFuncAttributeMaxDynamicSharedMemorySize,
                         (int)smem_bytes);
    TemPred_kernel<<<B_ / NB, THREADS, smem_bytes>>>(
        x_seq, Wih_e, Whh_e, bih_e, bhh_e,
        Wih_d, Whh_d, bih_d, bhh_d, Wl, bl, out);
}